// round 12
// baseline (speedup 1.0000x reference)
#include <cuda_runtime.h>
#include <cuda_fp16.h>
#include <mma.h>
#include <math.h>

using namespace nvcuda;

#define N_NODES 50000
#define N_EDGES 640000
#define N_GRAPHS 64
#define D 128
#define SCAN_B ((N_NODES + 255) / 256)   // 196

// ---------------- device scratch (no allocation allowed) ----------------
__device__ __half  g_xph[N_NODES * D];   // xp in fp16 (gather operand)
__device__ float   g_h [N_NODES * D];    // final-layer output fp32 (for pool)
__device__ __half  g_hh[N_NODES * D];    // layer output fp16 (GEMM A operand)
__device__ __half  g_whi[2 * D * D];     // fp16 hi part of w_lin1/2
__device__ __half  g_wlo[2 * D * D];     // fp16 lo (residual) part
__device__ float2  g_si[N_NODES];        // per-node dst-attention dots (2 heads)
__device__ float2  g_sj[N_NODES];        // per-node src-attention dots
__device__ float   g_ae[36];             // 3 layers x 6 feats x 2 heads
__device__ float2  g_seS[3 * N_EDGES];   // per-edge edge-att scores, dst-sorted, per layer
__device__ int     g_srcs[N_EDGES];      // src ids sorted by dst
__device__ int     g_deg[N_NODES];
__device__ int     g_off[N_NODES + 1];
__device__ int     g_cur[N_NODES];
__device__ int     g_ticket;                      // lookback scan ticket
__device__ unsigned long long g_state[SCAN_B];    // flag<<32 | value
__device__ float   g_pool[N_GRAPHS * D];
__device__ float   g_cnt[N_GRAPHS];
__device__ int     g_flags[2];           // [0]: edge_index is int64, [1]: batch is int64

// ---- init: zero deg/pool/cnt/scan-state + dtype detect + attproj + wsplit
__global__ void init_kernel(const int* __restrict__ ei32, const int* __restrict__ b32,
                            const float* __restrict__ we0, const float* __restrict__ at0,
                            const float* __restrict__ we1, const float* __restrict__ at1,
                            const float* __restrict__ we2, const float* __restrict__ at2,
                            const float* __restrict__ w1,  const float* __restrict__ w2) {
    int t = threadIdx.x;
    int gid = blockIdx.x * 256 + t;
    if (gid < N_NODES) g_deg[gid] = 0;
    if (gid < N_GRAPHS * D) g_pool[gid] = 0.f;
    if (gid < N_GRAPHS) g_cnt[gid] = 0.f;
    if (gid < SCAN_B) g_state[gid] = 0ULL;
    if (gid == 0) g_ticket = 0;
    // split-W precompute: 2*128*128 = 32768 elements
    if (gid < 2 * D * D) {
        const float* w = (gid < D * D) ? w1 : w2;
        float v = w[gid & (D * D - 1)];
        __half h = __float2half_rn(v);
        g_whi[gid] = h;
        g_wlo[gid] = __float2half_rn(v - __half2float(h));
    }
    if (blockIdx.x == 0) {
        __shared__ int s_e, s_b;
        if (t == 0) { s_e = 0; s_b = 0; }
        __syncthreads();
        if (t < 64) {
            // int64 data (values < 2^31) has all-zero odd 32-bit words
            int ei_idx = 2 * (t * 257) + 1;
            if (ei32[ei_idx] != 0) atomicAdd(&s_e, 1);
            int b_idx = (N_NODES - 1) - 2 * t;   // batch sorted: sample near tail
            if (b32[b_idx] != 0) atomicAdd(&s_b, 1);
        }
        __syncthreads();
        if (t == 0) { g_flags[0] = (s_e == 0); g_flags[1] = (s_b == 0); }
        if (t < 36) {
            int l = t / 12, r = t % 12, f = r / 2, h = r % 2;
            const float* we = (l == 0) ? we0 : (l == 1) ? we1 : we2;
            const float* at = (l == 0) ? at0 : (l == 1) ? at1 : at2;
            float s = 0.f;
            #pragma unroll
            for (int c = 0; c < 64; c++)
                s += we[f * 128 + h * 64 + c] * at[h * 192 + 128 + c];
            g_ae[t] = s;
        }
    }
}

__device__ __forceinline__ void load_edge(const void* ei, int e, int& src, int& dst) {
    if (g_flags[0]) {
        const long long* p = (const long long*)ei;
        src = (int)p[e]; dst = (int)p[N_EDGES + e];
    } else {
        const int* p = (const int*)ei;
        src = p[e]; dst = p[N_EDGES + e];
    }
}

// ---------------------------- CSR build ----------------------------------
__global__ void deg_kernel(const void* __restrict__ ei) {
    int e = blockIdx.x * blockDim.x + threadIdx.x;
    if (e >= N_EDGES) return;
    int src, dst; load_edge(ei, e, src, dst);
    atomicAdd(&g_deg[dst], 1);
}

// single-pass decoupled-lookback exclusive scan of g_deg -> g_off/g_cur
__global__ void scan_lookback_kernel() {
    __shared__ int sh[256];
    __shared__ int s_bid, s_prefix;
    int t = threadIdx.x;
    if (t == 0) s_bid = atomicAdd(&g_ticket, 1);
    __syncthreads();
    int bid = s_bid;
    int i = bid * 256 + t;
    int v = (i < N_NODES) ? g_deg[i] : 0;
    sh[t] = v; __syncthreads();
    #pragma unroll
    for (int off = 1; off < 256; off <<= 1) {
        int u = (t >= off) ? sh[t - off] : 0;
        __syncthreads();
        sh[t] += u;
        __syncthreads();
    }
    int aggregate = sh[255];
    if (t == 0) {
        // publish: bid 0 can publish final prefix (flag 2) immediately
        unsigned long long st = (bid == 0)
            ? (2ULL << 32) | (unsigned)aggregate
            : (1ULL << 32) | (unsigned)aggregate;
        atomicExch(&g_state[bid], st);
        // lookback
        int prefix = 0;
        for (int j = bid - 1; j >= 0; j--) {
            unsigned long long st2;
            while (((st2 = atomicAdd(&g_state[j], 0ULL)) >> 32) == 0ULL)
                __nanosleep(20);
            prefix += (int)(unsigned)st2;
            if ((st2 >> 32) == 2ULL) break;
        }
        s_prefix = prefix;
        if (bid != 0)
            atomicExch(&g_state[bid], (2ULL << 32) | (unsigned)(prefix + aggregate));
    }
    __syncthreads();
    int prefix = s_prefix;
    if (i < N_NODES) {
        int o = prefix + sh[t] - v;     // exclusive
        g_off[i] = o; g_cur[i] = o;
    }
    if (i == 0) g_off[N_NODES] = N_EDGES;
}

// scatter src + per-edge se (all 3 layers) into dst-sorted order
__global__ void scatter_kernel(const void* __restrict__ ei,
                               const float* __restrict__ ea) {
    int e = blockIdx.x * blockDim.x + threadIdx.x;
    if (e >= N_EDGES) return;
    int src, dst; load_edge(ei, e, src, dst);
    int pos = atomicAdd(&g_cur[dst], 1);
    g_srcs[pos] = src;
    float f[6];
    #pragma unroll
    for (int k = 0; k < 6; k++) f[k] = __ldg(ea + e * 6 + k);
    #pragma unroll
    for (int l = 0; l < 3; l++) {
        const float* ap = g_ae + l * 12;
        float s0 = 0.f, s1 = 0.f;
        #pragma unroll
        for (int k = 0; k < 6; k++) { s0 += f[k] * ap[k * 2]; s1 += f[k] * ap[k * 2 + 1]; }
        g_seS[l * N_EDGES + pos] = make_float2(s0, s1);
    }
}

// ---- layer-0 lin + s-dots fused: warp per node, x(N,7) @ w(7,128) -------
__global__ void lin0s_kernel(const float* __restrict__ x, const float* __restrict__ w,
                             const float* __restrict__ att) {
    int node = (blockIdx.x * blockDim.x + threadIdx.x) >> 5;
    int lane = threadIdx.x & 31;
    if (node >= N_NODES) return;
    float xr[7];
    #pragma unroll
    for (int f = 0; f < 7; f++) xr[f] = x[node * 7 + f];
    int c0 = lane * 4;
    float v[4];
    #pragma unroll
    for (int k = 0; k < 4; k++) {
        float s = 0.f;
        #pragma unroll
        for (int f = 0; f < 7; f++) s += xr[f] * w[f * 128 + c0 + k];
        v[k] = s;
    }
    ((__half2*)(g_xph + (size_t)node * 128))[lane * 2]     = __floats2half2_rn(v[0], v[1]);
    ((__half2*)(g_xph + (size_t)node * 128))[lane * 2 + 1] = __floats2half2_rn(v[2], v[3]);
    int h  = c0 >> 6;
    const float* ai = att + h * 192;
    const float* aj = ai + 64;
    int cc = c0 & 63;
    float si_p = v[0] * ai[cc] + v[1] * ai[cc + 1] + v[2] * ai[cc + 2] + v[3] * ai[cc + 3];
    float sj_p = v[0] * aj[cc] + v[1] * aj[cc + 1] + v[2] * aj[cc + 2] + v[3] * aj[cc + 3];
    #pragma unroll
    for (int o = 8; o; o >>= 1) {
        si_p += __shfl_down_sync(0xffffffffu, si_p, o, 16);
        sj_p += __shfl_down_sync(0xffffffffu, sj_p, o, 16);
    }
    float si1 = __shfl_sync(0xffffffffu, si_p, 16);
    float sj1 = __shfl_sync(0xffffffffu, sj_p, 16);
    if (lane == 0) {
        g_si[node] = make_float2(si_p, si1);
        g_sj[node] = make_float2(sj_p, sj1);
    }
}

// ---- lin (layers 1,2): hh fp16 @ (W_hi + W_lo) -> g_xph + s-dots --------
// WMMA 16x16x16, fp32 accumulate, split-W precomputed in fp16.
__global__ void __launch_bounds__(256) lin128_wmma(const __half* __restrict__ hh,
                                                   int widx,
                                                   const float* __restrict__ att) {
    __shared__ __align__(32) unsigned char smem_raw[34816];
    __half* As  = (__half*)smem_raw;                 // [64][136]
    __half* Bhi = (__half*)(smem_raw + 17408);       // [32][136]
    __half* Blo = (__half*)(smem_raw + 26112);       // [32][136]
    float*  Cs  = (float*)smem_raw;                  // [64][132] after K loop

    const __half* whi = g_whi + widx * D * D;
    const __half* wlo = g_wlo + widx * D * D;

    int t = threadIdx.x;
    int wid = t >> 5, lane = t & 31;
    int row0 = blockIdx.x * 64;

    for (int i = t; i < 64 * 32; i += 256) {
        int r = i >> 5, g = i & 31;
        int row = row0 + r;
        uint2 v = make_uint2(0u, 0u);
        if (row < N_NODES) v = *(const uint2*)(hh + (size_t)row * 128 + g * 4);
        *(uint2*)(As + r * 136 + g * 4) = v;
    }

    wmma::fragment<wmma::accumulator, 16, 16, 16, float> c[4];
    #pragma unroll
    for (int j = 0; j < 4; j++) wmma::fill_fragment(c[j], 0.f);

    int m_tile = wid & 3;
    int n_half = wid >> 2;

    for (int kc = 0; kc < 4; kc++) {
        int k0 = kc * 32;
        for (int i = t; i < 32 * 32; i += 256) {
            int r = i >> 5, g = i & 31;
            *(uint2*)(Bhi + r * 136 + g * 4) = *(const uint2*)(whi + (size_t)(k0 + r) * 128 + g * 4);
            *(uint2*)(Blo + r * 136 + g * 4) = *(const uint2*)(wlo + (size_t)(k0 + r) * 128 + g * 4);
        }
        __syncthreads();
        #pragma unroll
        for (int kk = 0; kk < 2; kk++) {
            int k = k0 + kk * 16;
            wmma::fragment<wmma::matrix_a, 16, 16, 16, __half, wmma::row_major> a;
            wmma::load_matrix_sync(a, As + m_tile * 16 * 136 + k, 136);
            #pragma unroll
            for (int j = 0; j < 4; j++) {
                wmma::fragment<wmma::matrix_b, 16, 16, 16, __half, wmma::row_major> b;
                wmma::load_matrix_sync(b, Bhi + (kk * 16) * 136 + n_half * 64 + j * 16, 136);
                wmma::mma_sync(c[j], a, b, c[j]);
                wmma::load_matrix_sync(b, Blo + (kk * 16) * 136 + n_half * 64 + j * 16, 136);
                wmma::mma_sync(c[j], a, b, c[j]);
            }
        }
        __syncthreads();
    }

    #pragma unroll
    for (int j = 0; j < 4; j++)
        wmma::store_matrix_sync(Cs + m_tile * 16 * 132 + n_half * 64 + j * 16,
                                c[j], 132, wmma::mem_row_major);
    __syncthreads();

    for (int r8 = 0; r8 < 8; r8++) {
        int r = wid * 8 + r8;
        int row = row0 + r;
        if (row >= N_NODES) break;
        const float* cr = Cs + r * 132;
        float v0 = cr[lane * 4], v1 = cr[lane * 4 + 1];
        float v2 = cr[lane * 4 + 2], v3 = cr[lane * 4 + 3];
        ((__half2*)(g_xph + (size_t)row * 128))[lane * 2]     = __floats2half2_rn(v0, v1);
        ((__half2*)(g_xph + (size_t)row * 128))[lane * 2 + 1] = __floats2half2_rn(v2, v3);
        int c0 = lane * 4;
        int h  = c0 >> 6;
        const float* ai = att + h * 192;
        const float* aj = att + h * 192 + 64;
        int cc = c0 & 63;
        float si_p = v0 * ai[cc] + v1 * ai[cc + 1] + v2 * ai[cc + 2] + v3 * ai[cc + 3];
        float sj_p = v0 * aj[cc] + v1 * aj[cc + 1] + v2 * aj[cc + 2] + v3 * aj[cc + 3];
        #pragma unroll
        for (int o = 8; o; o >>= 1) {
            si_p += __shfl_down_sync(0xffffffffu, si_p, o, 16);
            sj_p += __shfl_down_sync(0xffffffffu, sj_p, o, 16);
        }
        float si1 = __shfl_sync(0xffffffffu, si_p, 16);
        float sj1 = __shfl_sync(0xffffffffu, sj_p, 16);
        if (lane == 0) {
            g_si[row] = make_float2(si_p, si1);
            g_sj[row] = make_float2(sj_p, sj1);
        }
    }
}

// ------- aggregate: warp/dst, 2-edge unrolled, sigmoid softmax -----------
__device__ __forceinline__ float lrelu(float v) { return v > 0.f ? v : 0.2f * v; }

__global__ void __launch_bounds__(256) agg_kernel(const float* __restrict__ b, int layer) {
    int node = (blockIdx.x * blockDim.x + threadIdx.x) >> 5;
    int lane = threadIdx.x & 31;
    if (node >= N_NODES) return;
    int beg = g_off[node], end = g_off[node + 1];
    float2 si = g_si[node];
    const float2* seL = g_seS + (size_t)layer * N_EDGES;
    float4 acc = make_float4(0.f, 0.f, 0.f, 0.f);
    float sgn = (lane < 16) ? 1.f : -1.f;

    int i = beg;
    for (; i + 2 <= end; i += 2) {
        int s0 = g_srcs[i], s1 = g_srcs[i + 1];
        float2 se0 = seL[i], se1 = seL[i + 1];
        float2 sj0 = g_sj[s0], sj1 = g_sj[s1];
        uint2 r0 = ((const uint2*)(g_xph + (size_t)s0 * D))[lane];
        uint2 r1 = ((const uint2*)(g_xph + (size_t)s1 * D))[lane];

        float d0 = lrelu(si.x + sj0.x + se0.x) - lrelu(si.y + sj0.y + se0.y);
        float w0 = 1.f / (1.f + __expf(-sgn * d0));
        float2 f0 = __half22float2(*reinterpret_cast<__half2*>(&r0.x));
        float2 f1 = __half22float2(*reinterpret_cast<__half2*>(&r0.y));
        acc.x += w0 * f0.x; acc.y += w0 * f0.y;
        acc.z += w0 * f1.x; acc.w += w0 * f1.y;

        float d1 = lrelu(si.x + sj1.x + se1.x) - lrelu(si.y + sj1.y + se1.y);
        float w1 = 1.f / (1.f + __expf(-sgn * d1));
        float2 g0 = __half22float2(*reinterpret_cast<__half2*>(&r1.x));
        float2 g1 = __half22float2(*reinterpret_cast<__half2*>(&r1.y));
        acc.x += w1 * g0.x; acc.y += w1 * g0.y;
        acc.z += w1 * g1.x; acc.w += w1 * g1.y;
    }
    if (i < end) {
        int s0 = g_srcs[i];
        float2 se0 = seL[i];
        float2 sj0 = g_sj[s0];
        uint2 r0 = ((const uint2*)(g_xph + (size_t)s0 * D))[lane];
        float d0 = lrelu(si.x + sj0.x + se0.x) - lrelu(si.y + sj0.y + se0.y);
        float w0 = 1.f / (1.f + __expf(-sgn * d0));
        float2 f0 = __half22float2(*reinterpret_cast<__half2*>(&r0.x));
        float2 f1 = __half22float2(*reinterpret_cast<__half2*>(&r0.y));
        acc.x += w0 * f0.x; acc.y += w0 * f0.y;
        acc.z += w0 * f1.x; acc.w += w0 * f1.y;
    }
    float4 bv = ((const float4*)b)[lane];
    acc.x = fmaxf(acc.x + bv.x, 0.f);
    acc.y = fmaxf(acc.y + bv.y, 0.f);
    acc.z = fmaxf(acc.z + bv.z, 0.f);
    acc.w = fmaxf(acc.w + bv.w, 0.f);
    if (layer == 2) {
        ((float4*)(g_h + (size_t)node * D))[lane] = acc;   // pool input, fp32
    } else {
        ((__half2*)(g_hh + (size_t)node * D))[lane * 2]     = __floats2half2_rn(acc.x, acc.y);
        ((__half2*)(g_hh + (size_t)node * D))[lane * 2 + 1] = __floats2half2_rn(acc.z, acc.w);
    }
}

// ------------- mean pool: batch is sorted, run-length local accum --------
__global__ void pool_kernel(const void* __restrict__ batch) {
    const int NPB = 128;
    int t  = threadIdx.x;
    int n0 = blockIdx.x * NPB;
    int is64 = g_flags[1];
    float acc = 0.f; int cur = -1; int run = 0;
    for (int k = 0; k < NPB; k++) {
        int n = n0 + k;
        if (n >= N_NODES) break;
        int g = is64 ? (int)((const long long*)batch)[n] : ((const int*)batch)[n];
        if (g != cur) {
            if (cur >= 0) {
                atomicAdd(&g_pool[cur * D + t], acc);
                if (t == 0) atomicAdd(&g_cnt[cur], (float)run);
            }
            acc = 0.f; run = 0; cur = g;
        }
        acc += g_h[n * D + t]; run++;
    }
    if (cur >= 0) {
        atomicAdd(&g_pool[cur * D + t], acc);
        if (t == 0) atomicAdd(&g_cnt[cur], (float)run);
    }
}

// --------- final: warp per graph — mean, linear(128->2), log_softmax -----
__global__ void final_kernel(const float* __restrict__ wout,
                             const float* __restrict__ bout,
                             float* __restrict__ out) {
    int g    = (blockIdx.x * blockDim.x + threadIdx.x) >> 5;
    int lane = threadIdx.x & 31;
    if (g >= N_GRAPHS) return;
    float inv = 1.f / fmaxf(g_cnt[g], 1.f);
    float z0 = 0.f, z1 = 0.f;
    #pragma unroll
    for (int k = 0; k < 4; k++) {
        int c = lane + k * 32;
        float p = g_pool[g * D + c] * inv;
        z0 += p * wout[c * 2];
        z1 += p * wout[c * 2 + 1];
    }
    #pragma unroll
    for (int o = 16; o; o >>= 1) {
        z0 += __shfl_down_sync(0xffffffffu, z0, o);
        z1 += __shfl_down_sync(0xffffffffu, z1, o);
    }
    if (lane == 0) {
        z0 += bout[0]; z1 += bout[1];
        float m = fmaxf(z0, z1);
        float l = m + logf(expf(z0 - m) + expf(z1 - m));
        out[g * 2]     = z0 - l;
        out[g * 2 + 1] = z1 - l;
    }
}

// ------------------------------ launch -----------------------------------
extern "C" void kernel_launch(void* const* d_in, const int* in_sizes, int n_in,
                              void* d_out, int out_size) {
    const float* x     = (const float*)d_in[0];
    const void*  ei    = d_in[1];
    const float* ea    = (const float*)d_in[2];
    const void*  batch = d_in[3];
    const float* wl[3]  = { (const float*)d_in[4],  (const float*)d_in[8],  (const float*)d_in[12] };
    const float* we[3]  = { (const float*)d_in[5],  (const float*)d_in[9],  (const float*)d_in[13] };
    const float* att[3] = { (const float*)d_in[6],  (const float*)d_in[10], (const float*)d_in[14] };
    const float* bb[3]  = { (const float*)d_in[7],  (const float*)d_in[11], (const float*)d_in[15] };
    const float* wout = (const float*)d_in[16];
    const float* bout = (const float*)d_in[17];

    void* p_hh = nullptr;
    cudaGetSymbolAddress(&p_hh, g_hh);

    const int EB = (N_EDGES + 255) / 256;

    // init: zero scratch + dtype detect + attproj + wsplit (196 blocks)
    init_kernel<<<SCAN_B, 256>>>((const int*)ei, (const int*)batch,
                                 we[0], att[0], we[1], att[1], we[2], att[2],
                                 wl[1], wl[2]);

    // CSR build + sorted se (once per call)
    deg_kernel<<<EB, 256>>>(ei);
    scan_lookback_kernel<<<SCAN_B, 256>>>();
    scatter_kernel<<<EB, 256>>>(ei, ea);

    for (int l = 0; l < 3; l++) {
        if (l == 0) {
            lin0s_kernel<<<(N_NODES * 32 + 255) / 256, 256>>>(x, wl[0], att[0]);
        } else {
            lin128_wmma<<<(N_NODES + 63) / 64, 256>>>((const __half*)p_hh, l - 1, att[l]);
        }
        agg_kernel<<<(N_NODES * 32 + 255) / 256, 256>>>(bb[l], l);
    }

    pool_kernel<<<(N_NODES + 127) / 128, 128>>>(batch);
    final_kernel<<<2, 1024>>>(wout, bout, (float*)d_out);
}

// round 13
// speedup vs baseline: 1.0335x; 1.0335x over previous
#include <cuda_runtime.h>
#include <cuda_fp16.h>
#include <mma.h>
#include <math.h>

using namespace nvcuda;

#define N_NODES 50000
#define N_EDGES 640000
#define N_GRAPHS 64
#define D 128
#define SCAN_B ((N_NODES + 255) / 256)   // 196

// ---------------- device scratch (no allocation allowed) ----------------
__device__ __half  g_xph[N_NODES * D];   // xp in fp16 (gather operand)
__device__ float   g_h [N_NODES * D];    // final-layer output fp32 (for pool)
__device__ __half  g_hh[N_NODES * D];    // layer output fp16 (GEMM A operand)
__device__ __half  g_whi[2 * D * D];     // fp16 hi part of w_lin1/2
__device__ __half  g_wlo[2 * D * D];     // fp16 lo (residual) part
__device__ float2  g_si[N_NODES];        // per-node dst-attention dots (2 heads)
__device__ float2  g_sj[N_NODES];        // per-node src-attention dots
__device__ float   g_ae[36];             // 3 layers x 6 feats x 2 heads
__device__ float2  g_seS[3 * N_EDGES];   // per-edge edge-att scores, dst-sorted, per layer
__device__ int     g_srcs[N_EDGES];      // src ids sorted by dst
__device__ int     g_deg[N_NODES];
__device__ int     g_off[N_NODES + 1];
__device__ int     g_cur[N_NODES];
__device__ int     g_bsum[SCAN_B];
__device__ float   g_pool[N_GRAPHS * D];
__device__ float   g_cnt[N_GRAPHS];
__device__ int     g_flags[2];           // [0]: edge_index is int64, [1]: batch is int64

// ---- init: zero deg/pool/cnt + dtype detect + attproj + wsplit ----------
__global__ void init_kernel(const int* __restrict__ ei32, const int* __restrict__ b32,
                            const float* __restrict__ we0, const float* __restrict__ at0,
                            const float* __restrict__ we1, const float* __restrict__ at1,
                            const float* __restrict__ we2, const float* __restrict__ at2,
                            const float* __restrict__ w1,  const float* __restrict__ w2) {
    int t = threadIdx.x;
    int gid = blockIdx.x * 256 + t;
    if (gid < N_NODES) g_deg[gid] = 0;
    if (gid < N_GRAPHS * D) g_pool[gid] = 0.f;
    if (gid < N_GRAPHS) g_cnt[gid] = 0.f;
    // split-W precompute: 2*128*128 = 32768 elements
    if (gid < 2 * D * D) {
        const float* w = (gid < D * D) ? w1 : w2;
        float v = w[gid & (D * D - 1)];
        __half h = __float2half_rn(v);
        g_whi[gid] = h;
        g_wlo[gid] = __float2half_rn(v - __half2float(h));
    }
    if (blockIdx.x == 0) {
        __shared__ int s_e, s_b;
        if (t == 0) { s_e = 0; s_b = 0; }
        __syncthreads();
        if (t < 64) {
            // int64 data (values < 2^31) has all-zero odd 32-bit words
            int ei_idx = 2 * (t * 257) + 1;
            if (ei32[ei_idx] != 0) atomicAdd(&s_e, 1);
            int b_idx = (N_NODES - 1) - 2 * t;   // batch sorted: sample near tail
            if (b32[b_idx] != 0) atomicAdd(&s_b, 1);
        }
        __syncthreads();
        if (t == 0) { g_flags[0] = (s_e == 0); g_flags[1] = (s_b == 0); }
        if (t < 36) {
            int l = t / 12, r = t % 12, f = r / 2, h = r % 2;
            const float* we = (l == 0) ? we0 : (l == 1) ? we1 : we2;
            const float* at = (l == 0) ? at0 : (l == 1) ? at1 : at2;
            float s = 0.f;
            #pragma unroll
            for (int c = 0; c < 64; c++)
                s += we[f * 128 + h * 64 + c] * at[h * 192 + 128 + c];
            g_ae[t] = s;
        }
    }
}

__device__ __forceinline__ void load_edge(const void* ei, int e, int& src, int& dst) {
    if (g_flags[0]) {
        const long long* p = (const long long*)ei;
        src = (int)p[e]; dst = (int)p[N_EDGES + e];
    } else {
        const int* p = (const int*)ei;
        src = p[e]; dst = p[N_EDGES + e];
    }
}

// ------------------- CSR build: deg, 4 edges/thread ----------------------
__global__ void deg_kernel(const void* __restrict__ ei) {
    int e0 = (blockIdx.x * blockDim.x + threadIdx.x) * 4;
    if (e0 >= N_EDGES) return;
    int is64 = g_flags[0];
    int d0, d1, d2, d3;
    if (is64) {
        const long long* p = (const long long*)ei + N_EDGES;
        d0 = (int)p[e0]; d1 = (int)p[e0 + 1]; d2 = (int)p[e0 + 2]; d3 = (int)p[e0 + 3];
    } else {
        const int* p = (const int*)ei + N_EDGES;
        d0 = p[e0]; d1 = p[e0 + 1]; d2 = p[e0 + 2]; d3 = p[e0 + 3];
    }
    atomicAdd(&g_deg[d0], 1);
    atomicAdd(&g_deg[d1], 1);
    atomicAdd(&g_deg[d2], 1);
    atomicAdd(&g_deg[d3], 1);
}

// 3-phase exclusive scan of g_deg -> g_off/g_cur (verified config)
__global__ void scan1_kernel() {
    __shared__ int sh[256];
    int t = threadIdx.x;
    int i = blockIdx.x * 256 + t;
    int v = (i < N_NODES) ? g_deg[i] : 0;
    sh[t] = v; __syncthreads();
    #pragma unroll
    for (int off = 1; off < 256; off <<= 1) {
        int u = (t >= off) ? sh[t - off] : 0;
        __syncthreads();
        sh[t] += u;
        __syncthreads();
    }
    if (i < N_NODES) g_off[i] = sh[t] - v;
    if (t == 255) g_bsum[blockIdx.x] = sh[255];
}

__global__ void scan2_kernel() {
    __shared__ int sh[256];
    int t = threadIdx.x;
    int v = (t < SCAN_B) ? g_bsum[t] : 0;
    sh[t] = v; __syncthreads();
    #pragma unroll
    for (int off = 1; off < 256; off <<= 1) {
        int u = (t >= off) ? sh[t - off] : 0;
        __syncthreads();
        sh[t] += u;
        __syncthreads();
    }
    if (t < SCAN_B) g_bsum[t] = sh[t] - v;
}

__global__ void scan3_kernel() {
    int i = blockIdx.x * 256 + threadIdx.x;
    if (i < N_NODES) {
        int o = g_off[i] + g_bsum[blockIdx.x];
        g_off[i] = o; g_cur[i] = o;
    }
    if (i == 0) g_off[N_NODES] = N_EDGES;
}

// ---- scatter: 2 edges/thread — both atomics + writes in flight ----------
__global__ void scatter_kernel(const void* __restrict__ ei,
                               const float* __restrict__ ea) {
    int e0 = (blockIdx.x * blockDim.x + threadIdx.x) * 2;
    if (e0 >= N_EDGES) return;
    int e1 = e0 + 1;
    int s0, d0, s1, d1;
    load_edge(ei, e0, s0, d0);
    load_edge(ei, e1, s1, d1);
    float f0[6], f1[6];
    #pragma unroll
    for (int k = 0; k < 6; k++) f0[k] = __ldg(ea + e0 * 6 + k);
    #pragma unroll
    for (int k = 0; k < 6; k++) f1[k] = __ldg(ea + e1 * 6 + k);
    int p0 = atomicAdd(&g_cur[d0], 1);
    int p1 = atomicAdd(&g_cur[d1], 1);
    g_srcs[p0] = s0;
    g_srcs[p1] = s1;
    #pragma unroll
    for (int l = 0; l < 3; l++) {
        const float* ap = g_ae + l * 12;
        float a0 = 0.f, b0 = 0.f, a1 = 0.f, b1 = 0.f;
        #pragma unroll
        for (int k = 0; k < 6; k++) {
            a0 += f0[k] * ap[k * 2]; b0 += f0[k] * ap[k * 2 + 1];
            a1 += f1[k] * ap[k * 2]; b1 += f1[k] * ap[k * 2 + 1];
        }
        g_seS[l * N_EDGES + p0] = make_float2(a0, b0);
        g_seS[l * N_EDGES + p1] = make_float2(a1, b1);
    }
}

// ---- layer-0 lin + s-dots fused: warp per node, x(N,7) @ w(7,128) -------
__global__ void lin0s_kernel(const float* __restrict__ x, const float* __restrict__ w,
                             const float* __restrict__ att) {
    int node = (blockIdx.x * blockDim.x + threadIdx.x) >> 5;
    int lane = threadIdx.x & 31;
    if (node >= N_NODES) return;
    float xr[7];
    #pragma unroll
    for (int f = 0; f < 7; f++) xr[f] = x[node * 7 + f];
    int c0 = lane * 4;
    float v[4];
    #pragma unroll
    for (int k = 0; k < 4; k++) {
        float s = 0.f;
        #pragma unroll
        for (int f = 0; f < 7; f++) s += xr[f] * w[f * 128 + c0 + k];
        v[k] = s;
    }
    ((__half2*)(g_xph + (size_t)node * 128))[lane * 2]     = __floats2half2_rn(v[0], v[1]);
    ((__half2*)(g_xph + (size_t)node * 128))[lane * 2 + 1] = __floats2half2_rn(v[2], v[3]);
    int h  = c0 >> 6;
    const float* ai = att + h * 192;
    const float* aj = ai + 64;
    int cc = c0 & 63;
    float si_p = v[0] * ai[cc] + v[1] * ai[cc + 1] + v[2] * ai[cc + 2] + v[3] * ai[cc + 3];
    float sj_p = v[0] * aj[cc] + v[1] * aj[cc + 1] + v[2] * aj[cc + 2] + v[3] * aj[cc + 3];
    #pragma unroll
    for (int o = 8; o; o >>= 1) {
        si_p += __shfl_down_sync(0xffffffffu, si_p, o, 16);
        sj_p += __shfl_down_sync(0xffffffffu, sj_p, o, 16);
    }
    float si1 = __shfl_sync(0xffffffffu, si_p, 16);
    float sj1 = __shfl_sync(0xffffffffu, sj_p, 16);
    if (lane == 0) {
        g_si[node] = make_float2(si_p, si1);
        g_sj[node] = make_float2(sj_p, sj1);
    }
}

// ---- lin (layers 1,2): hh fp16 @ (W_hi + W_lo) -> g_xph + s-dots --------
__global__ void __launch_bounds__(256) lin128_wmma(const __half* __restrict__ hh,
                                                   int widx,
                                                   const float* __restrict__ att) {
    __shared__ __align__(32) unsigned char smem_raw[34816];
    __half* As  = (__half*)smem_raw;                 // [64][136]
    __half* Bhi = (__half*)(smem_raw + 17408);       // [32][136]
    __half* Blo = (__half*)(smem_raw + 26112);       // [32][136]
    float*  Cs  = (float*)smem_raw;                  // [64][132] after K loop

    const __half* whi = g_whi + widx * D * D;
    const __half* wlo = g_wlo + widx * D * D;

    int t = threadIdx.x;
    int wid = t >> 5, lane = t & 31;
    int row0 = blockIdx.x * 64;

    for (int i = t; i < 64 * 32; i += 256) {
        int r = i >> 5, g = i & 31;
        int row = row0 + r;
        uint2 v = make_uint2(0u, 0u);
        if (row < N_NODES) v = *(const uint2*)(hh + (size_t)row * 128 + g * 4);
        *(uint2*)(As + r * 136 + g * 4) = v;
    }

    wmma::fragment<wmma::accumulator, 16, 16, 16, float> c[4];
    #pragma unroll
    for (int j = 0; j < 4; j++) wmma::fill_fragment(c[j], 0.f);

    int m_tile = wid & 3;
    int n_half = wid >> 2;

    for (int kc = 0; kc < 4; kc++) {
        int k0 = kc * 32;
        for (int i = t; i < 32 * 32; i += 256) {
            int r = i >> 5, g = i & 31;
            *(uint2*)(Bhi + r * 136 + g * 4) = *(const uint2*)(whi + (size_t)(k0 + r) * 128 + g * 4);
            *(uint2*)(Blo + r * 136 + g * 4) = *(const uint2*)(wlo + (size_t)(k0 + r) * 128 + g * 4);
        }
        __syncthreads();
        #pragma unroll
        for (int kk = 0; kk < 2; kk++) {
            int k = k0 + kk * 16;
            wmma::fragment<wmma::matrix_a, 16, 16, 16, __half, wmma::row_major> a;
            wmma::load_matrix_sync(a, As + m_tile * 16 * 136 + k, 136);
            #pragma unroll
            for (int j = 0; j < 4; j++) {
                wmma::fragment<wmma::matrix_b, 16, 16, 16, __half, wmma::row_major> b;
                wmma::load_matrix_sync(b, Bhi + (kk * 16) * 136 + n_half * 64 + j * 16, 136);
                wmma::mma_sync(c[j], a, b, c[j]);
                wmma::load_matrix_sync(b, Blo + (kk * 16) * 136 + n_half * 64 + j * 16, 136);
                wmma::mma_sync(c[j], a, b, c[j]);
            }
        }
        __syncthreads();
    }

    #pragma unroll
    for (int j = 0; j < 4; j++)
        wmma::store_matrix_sync(Cs + m_tile * 16 * 132 + n_half * 64 + j * 16,
                                c[j], 132, wmma::mem_row_major);
    __syncthreads();

    for (int r8 = 0; r8 < 8; r8++) {
        int r = wid * 8 + r8;
        int row = row0 + r;
        if (row >= N_NODES) break;
        const float* cr = Cs + r * 132;
        float v0 = cr[lane * 4], v1 = cr[lane * 4 + 1];
        float v2 = cr[lane * 4 + 2], v3 = cr[lane * 4 + 3];
        ((__half2*)(g_xph + (size_t)row * 128))[lane * 2]     = __floats2half2_rn(v0, v1);
        ((__half2*)(g_xph + (size_t)row * 128))[lane * 2 + 1] = __floats2half2_rn(v2, v3);
        int c0 = lane * 4;
        int h  = c0 >> 6;
        const float* ai = att + h * 192;
        const float* aj = att + h * 192 + 64;
        int cc = c0 & 63;
        float si_p = v0 * ai[cc] + v1 * ai[cc + 1] + v2 * ai[cc + 2] + v3 * ai[cc + 3];
        float sj_p = v0 * aj[cc] + v1 * aj[cc + 1] + v2 * aj[cc + 2] + v3 * aj[cc + 3];
        #pragma unroll
        for (int o = 8; o; o >>= 1) {
            si_p += __shfl_down_sync(0xffffffffu, si_p, o, 16);
            sj_p += __shfl_down_sync(0xffffffffu, sj_p, o, 16);
        }
        float si1 = __shfl_sync(0xffffffffu, si_p, 16);
        float sj1 = __shfl_sync(0xffffffffu, sj_p, 16);
        if (lane == 0) {
            g_si[row] = make_float2(si_p, si1);
            g_sj[row] = make_float2(sj_p, sj1);
        }
    }
}

// ------- aggregate: warp/dst, 2-edge unrolled, sigmoid softmax -----------
__device__ __forceinline__ float lrelu(float v) { return v > 0.f ? v : 0.2f * v; }

__global__ void __launch_bounds__(256) agg_kernel(const float* __restrict__ b, int layer) {
    int node = (blockIdx.x * blockDim.x + threadIdx.x) >> 5;
    int lane = threadIdx.x & 31;
    if (node >= N_NODES) return;
    int beg = g_off[node], end = g_off[node + 1];
    float2 si = g_si[node];
    const float2* seL = g_seS + (size_t)layer * N_EDGES;
    float4 acc = make_float4(0.f, 0.f, 0.f, 0.f);
    float sgn = (lane < 16) ? 1.f : -1.f;

    int i = beg;
    for (; i + 2 <= end; i += 2) {
        int s0 = g_srcs[i], s1 = g_srcs[i + 1];
        float2 se0 = seL[i], se1 = seL[i + 1];
        float2 sj0 = g_sj[s0], sj1 = g_sj[s1];
        uint2 r0 = ((const uint2*)(g_xph + (size_t)s0 * D))[lane];
        uint2 r1 = ((const uint2*)(g_xph + (size_t)s1 * D))[lane];

        float d0 = lrelu(si.x + sj0.x + se0.x) - lrelu(si.y + sj0.y + se0.y);
        float w0 = 1.f / (1.f + __expf(-sgn * d0));
        float2 f0 = __half22float2(*reinterpret_cast<__half2*>(&r0.x));
        float2 f1 = __half22float2(*reinterpret_cast<__half2*>(&r0.y));
        acc.x += w0 * f0.x; acc.y += w0 * f0.y;
        acc.z += w0 * f1.x; acc.w += w0 * f1.y;

        float d1 = lrelu(si.x + sj1.x + se1.x) - lrelu(si.y + sj1.y + se1.y);
        float w1 = 1.f / (1.f + __expf(-sgn * d1));
        float2 g0 = __half22float2(*reinterpret_cast<__half2*>(&r1.x));
        float2 g1 = __half22float2(*reinterpret_cast<__half2*>(&r1.y));
        acc.x += w1 * g0.x; acc.y += w1 * g0.y;
        acc.z += w1 * g1.x; acc.w += w1 * g1.y;
    }
    if (i < end) {
        int s0 = g_srcs[i];
        float2 se0 = seL[i];
        float2 sj0 = g_sj[s0];
        uint2 r0 = ((const uint2*)(g_xph + (size_t)s0 * D))[lane];
        float d0 = lrelu(si.x + sj0.x + se0.x) - lrelu(si.y + sj0.y + se0.y);
        float w0 = 1.f / (1.f + __expf(-sgn * d0));
        float2 f0 = __half22float2(*reinterpret_cast<__half2*>(&r0.x));
        float2 f1 = __half22float2(*reinterpret_cast<__half2*>(&r0.y));
        acc.x += w0 * f0.x; acc.y += w0 * f0.y;
        acc.z += w0 * f1.x; acc.w += w0 * f1.y;
    }
    float4 bv = ((const float4*)b)[lane];
    acc.x = fmaxf(acc.x + bv.x, 0.f);
    acc.y = fmaxf(acc.y + bv.y, 0.f);
    acc.z = fmaxf(acc.z + bv.z, 0.f);
    acc.w = fmaxf(acc.w + bv.w, 0.f);
    if (layer == 2) {
        ((float4*)(g_h + (size_t)node * D))[lane] = acc;   // pool input, fp32
    } else {
        ((__half2*)(g_hh + (size_t)node * D))[lane * 2]     = __floats2half2_rn(acc.x, acc.y);
        ((__half2*)(g_hh + (size_t)node * D))[lane * 2 + 1] = __floats2half2_rn(acc.z, acc.w);
    }
}

// ------------- mean pool: batch is sorted, run-length local accum --------
__global__ void pool_kernel(const void* __restrict__ batch) {
    const int NPB = 128;
    int t  = threadIdx.x;
    int n0 = blockIdx.x * NPB;
    int is64 = g_flags[1];
    float acc = 0.f; int cur = -1; int run = 0;
    for (int k = 0; k < NPB; k++) {
        int n = n0 + k;
        if (n >= N_NODES) break;
        int g = is64 ? (int)((const long long*)batch)[n] : ((const int*)batch)[n];
        if (g != cur) {
            if (cur >= 0) {
                atomicAdd(&g_pool[cur * D + t], acc);
                if (t == 0) atomicAdd(&g_cnt[cur], (float)run);
            }
            acc = 0.f; run = 0; cur = g;
        }
        acc += g_h[n * D + t]; run++;
    }
    if (cur >= 0) {
        atomicAdd(&g_pool[cur * D + t], acc);
        if (t == 0) atomicAdd(&g_cnt[cur], (float)run);
    }
}

// --------- final: warp per graph — mean, linear(128->2), log_softmax -----
__global__ void final_kernel(const float* __restrict__ wout,
                             const float* __restrict__ bout,
                             float* __restrict__ out) {
    int g    = (blockIdx.x * blockDim.x + threadIdx.x) >> 5;
    int lane = threadIdx.x & 31;
    if (g >= N_GRAPHS) return;
    float inv = 1.f / fmaxf(g_cnt[g], 1.f);
    float z0 = 0.f, z1 = 0.f;
    #pragma unroll
    for (int k = 0; k < 4; k++) {
        int c = lane + k * 32;
        float p = g_pool[g * D + c] * inv;
        z0 += p * wout[c * 2];
        z1 += p * wout[c * 2 + 1];
    }
    #pragma unroll
    for (int o = 16; o; o >>= 1) {
        z0 += __shfl_down_sync(0xffffffffu, z0, o);
        z1 += __shfl_down_sync(0xffffffffu, z1, o);
    }
    if (lane == 0) {
        z0 += bout[0]; z1 += bout[1];
        float m = fmaxf(z0, z1);
        float l = m + logf(expf(z0 - m) + expf(z1 - m));
        out[g * 2]     = z0 - l;
        out[g * 2 + 1] = z1 - l;
    }
}

// ------------------------------ launch -----------------------------------
extern "C" void kernel_launch(void* const* d_in, const int* in_sizes, int n_in,
                              void* d_out, int out_size) {
    const float* x     = (const float*)d_in[0];
    const void*  ei    = d_in[1];
    const float* ea    = (const float*)d_in[2];
    const void*  batch = d_in[3];
    const float* wl[3]  = { (const float*)d_in[4],  (const float*)d_in[8],  (const float*)d_in[12] };
    const float* we[3]  = { (const float*)d_in[5],  (const float*)d_in[9],  (const float*)d_in[13] };
    const float* att[3] = { (const float*)d_in[6],  (const float*)d_in[10], (const float*)d_in[14] };
    const float* bb[3]  = { (const float*)d_in[7],  (const float*)d_in[11], (const float*)d_in[15] };
    const float* wout = (const float*)d_in[16];
    const float* bout = (const float*)d_in[17];

    void* p_hh = nullptr;
    cudaGetSymbolAddress(&p_hh, g_hh);

    // init: zero scratch + dtype detect + attproj + wsplit (196 blocks)
    init_kernel<<<SCAN_B, 256>>>((const int*)ei, (const int*)batch,
                                 we[0], att[0], we[1], att[1], we[2], att[2],
                                 wl[1], wl[2]);

    // CSR build + sorted se (once per call)
    deg_kernel<<<(N_EDGES / 4 + 255) / 256, 256>>>(ei);
    scan1_kernel<<<SCAN_B, 256>>>();
    scan2_kernel<<<1, 256>>>();
    scan3_kernel<<<SCAN_B, 256>>>();
    scatter_kernel<<<(N_EDGES / 2 + 255) / 256, 256>>>(ei, ea);

    for (int l = 0; l < 3; l++) {
        if (l == 0) {
            lin0s_kernel<<<(N_NODES * 32 + 255) / 256, 256>>>(x, wl[0], att[0]);
        } else {
            lin128_wmma<<<(N_NODES + 63) / 64, 256>>>((const __half*)p_hh, l - 1, att[l]);
        }
        agg_kernel<<<(N_NODES * 32 + 255) / 256, 256>>>(bb[l], l);
    }

    pool_kernel<<<(N_NODES + 127) / 128, 128>>>(batch);
    final_kernel<<<2, 1024>>>(wout, bout, (float*)d_out);
}

// round 14
// speedup vs baseline: 1.0828x; 1.0477x over previous
#include <cuda_runtime.h>
#include <cuda_fp16.h>
#include <mma.h>
#include <math.h>

using namespace nvcuda;

#define N_NODES 50000
#define N_EDGES 640000
#define N_GRAPHS 64
#define D 128
#define SCAN_B ((N_NODES + 255) / 256)   // 196

// ---------------- device scratch (no allocation allowed) ----------------
__device__ __half  g_xph[N_NODES * D];   // xp in fp16 (gather operand)
__device__ __half  g_hh[N_NODES * D];    // layer output fp16 (GEMM A operand + pool input)
__device__ __half  g_whi[2 * D * D];     // fp16 hi part of w_lin1/2
__device__ __half  g_wlo[2 * D * D];     // fp16 lo (residual) part
__device__ float2  g_si[N_NODES];        // per-node dst-attention dots (2 heads)
__device__ float2  g_sj[N_NODES];        // per-node src-attention dots
__device__ float   g_ae[36];             // 3 layers x 6 feats x 2 heads
__device__ float2  g_seS[3 * N_EDGES];   // per-edge edge-att scores, dst-sorted, per layer
__device__ int     g_srcs[N_EDGES];      // src ids sorted by dst
__device__ int     g_deg[N_NODES];
__device__ int     g_off[N_NODES + 1];
__device__ int     g_cur[N_NODES];
__device__ int     g_bsum[SCAN_B];
__device__ int     g_done;               // scan1 last-block ticket
__device__ float   g_pool[N_GRAPHS * D];
__device__ float   g_cnt[N_GRAPHS];
__device__ int     g_flags[2];           // [0]: edge_index is int64, [1]: batch is int64

// ---- init: zero deg/pool/cnt/done + dtype detect + attproj + wsplit -----
__global__ void init_kernel(const int* __restrict__ ei32, const int* __restrict__ b32,
                            const float* __restrict__ we0, const float* __restrict__ at0,
                            const float* __restrict__ we1, const float* __restrict__ at1,
                            const float* __restrict__ we2, const float* __restrict__ at2,
                            const float* __restrict__ w1,  const float* __restrict__ w2) {
    int t = threadIdx.x;
    int gid = blockIdx.x * 256 + t;
    if (gid < N_NODES) g_deg[gid] = 0;
    if (gid < N_GRAPHS * D) g_pool[gid] = 0.f;
    if (gid < N_GRAPHS) g_cnt[gid] = 0.f;
    if (gid == 0) g_done = 0;
    // split-W precompute: 2*128*128 = 32768 elements
    if (gid < 2 * D * D) {
        const float* w = (gid < D * D) ? w1 : w2;
        float v = w[gid & (D * D - 1)];
        __half h = __float2half_rn(v);
        g_whi[gid] = h;
        g_wlo[gid] = __float2half_rn(v - __half2float(h));
    }
    if (blockIdx.x == 0) {
        __shared__ int s_e, s_b;
        if (t == 0) { s_e = 0; s_b = 0; }
        __syncthreads();
        if (t < 64) {
            // int64 data (values < 2^31) has all-zero odd 32-bit words
            int ei_idx = 2 * (t * 257) + 1;
            if (ei32[ei_idx] != 0) atomicAdd(&s_e, 1);
            int b_idx = (N_NODES - 1) - 2 * t;   // batch sorted: sample near tail
            if (b32[b_idx] != 0) atomicAdd(&s_b, 1);
        }
        __syncthreads();
        if (t == 0) { g_flags[0] = (s_e == 0); g_flags[1] = (s_b == 0); }
        if (t < 36) {
            int l = t / 12, r = t % 12, f = r / 2, h = r % 2;
            const float* we = (l == 0) ? we0 : (l == 1) ? we1 : we2;
            const float* at = (l == 0) ? at0 : (l == 1) ? at1 : at2;
            float s = 0.f;
            #pragma unroll
            for (int c = 0; c < 64; c++)
                s += we[f * 128 + h * 64 + c] * at[h * 192 + 128 + c];
            g_ae[t] = s;
        }
    }
}

__device__ __forceinline__ void load_edge(const void* ei, int e, int& src, int& dst) {
    if (g_flags[0]) {
        const long long* p = (const long long*)ei;
        src = (int)p[e]; dst = (int)p[N_EDGES + e];
    } else {
        const int* p = (const int*)ei;
        src = p[e]; dst = p[N_EDGES + e];
    }
}

// ------------------- CSR build: deg, 4 edges/thread ----------------------
__global__ void deg_kernel(const void* __restrict__ ei) {
    int e0 = (blockIdx.x * blockDim.x + threadIdx.x) * 4;
    if (e0 >= N_EDGES) return;
    int is64 = g_flags[0];
    int d0, d1, d2, d3;
    if (is64) {
        const long long* p = (const long long*)ei + N_EDGES;
        d0 = (int)p[e0]; d1 = (int)p[e0 + 1]; d2 = (int)p[e0 + 2]; d3 = (int)p[e0 + 3];
    } else {
        const int* p = (const int*)ei + N_EDGES;
        d0 = p[e0]; d1 = p[e0 + 1]; d2 = p[e0 + 2]; d3 = p[e0 + 3];
    }
    atomicAdd(&g_deg[d0], 1);
    atomicAdd(&g_deg[d1], 1);
    atomicAdd(&g_deg[d2], 1);
    atomicAdd(&g_deg[d3], 1);
}

// scan1: block-local exclusive scan; the LAST block to finish also scans
// the 196 block sums (replaces the old scan2 launch).
__global__ void scan1_kernel() {
    __shared__ int sh[256];
    __shared__ bool isLast;
    int t = threadIdx.x;
    int i = blockIdx.x * 256 + t;
    int v = (i < N_NODES) ? g_deg[i] : 0;
    sh[t] = v; __syncthreads();
    #pragma unroll
    for (int off = 1; off < 256; off <<= 1) {
        int u = (t >= off) ? sh[t - off] : 0;
        __syncthreads();
        sh[t] += u;
        __syncthreads();
    }
    if (i < N_NODES) g_off[i] = sh[t] - v;
    if (t == 255) g_bsum[blockIdx.x] = sh[255];
    __threadfence();
    if (t == 0) {
        int d = atomicAdd(&g_done, 1);
        isLast = (d == (int)gridDim.x - 1);
    }
    __syncthreads();
    if (isLast) {
        int bv = (t < SCAN_B) ? ((volatile int*)g_bsum)[t] : 0;
        __syncthreads();           // sh reuse barrier
        sh[t] = bv; __syncthreads();
        #pragma unroll
        for (int off = 1; off < 256; off <<= 1) {
            int u = (t >= off) ? sh[t - off] : 0;
            __syncthreads();
            sh[t] += u;
            __syncthreads();
        }
        if (t < SCAN_B) g_bsum[t] = sh[t] - bv;   // exclusive block prefix
    }
}

__global__ void scan3_kernel() {
    int i = blockIdx.x * 256 + threadIdx.x;
    if (i < N_NODES) {
        int o = g_off[i] + g_bsum[blockIdx.x];
        g_off[i] = o; g_cur[i] = o;
    }
    if (i == 0) g_off[N_NODES] = N_EDGES;
}

// ---- scatter: 2 edges/thread — both atomics + writes in flight ----------
__global__ void scatter_kernel(const void* __restrict__ ei,
                               const float* __restrict__ ea) {
    int e0 = (blockIdx.x * blockDim.x + threadIdx.x) * 2;
    if (e0 >= N_EDGES) return;
    int e1 = e0 + 1;
    int s0, d0, s1, d1;
    load_edge(ei, e0, s0, d0);
    load_edge(ei, e1, s1, d1);
    float f0[6], f1[6];
    #pragma unroll
    for (int k = 0; k < 6; k++) f0[k] = __ldg(ea + e0 * 6 + k);
    #pragma unroll
    for (int k = 0; k < 6; k++) f1[k] = __ldg(ea + e1 * 6 + k);
    int p0 = atomicAdd(&g_cur[d0], 1);
    int p1 = atomicAdd(&g_cur[d1], 1);
    g_srcs[p0] = s0;
    g_srcs[p1] = s1;
    #pragma unroll
    for (int l = 0; l < 3; l++) {
        const float* ap = g_ae + l * 12;
        float a0 = 0.f, b0 = 0.f, a1 = 0.f, b1 = 0.f;
        #pragma unroll
        for (int k = 0; k < 6; k++) {
            a0 += f0[k] * ap[k * 2]; b0 += f0[k] * ap[k * 2 + 1];
            a1 += f1[k] * ap[k * 2]; b1 += f1[k] * ap[k * 2 + 1];
        }
        g_seS[l * N_EDGES + p0] = make_float2(a0, b0);
        g_seS[l * N_EDGES + p1] = make_float2(a1, b1);
    }
}

// ---- layer-0 lin + s-dots fused: warp per node, x(N,7) @ w(7,128) -------
__global__ void lin0s_kernel(const float* __restrict__ x, const float* __restrict__ w,
                             const float* __restrict__ att) {
    int node = (blockIdx.x * blockDim.x + threadIdx.x) >> 5;
    int lane = threadIdx.x & 31;
    if (node >= N_NODES) return;
    float xr[7];
    #pragma unroll
    for (int f = 0; f < 7; f++) xr[f] = x[node * 7 + f];
    int c0 = lane * 4;
    float v[4];
    #pragma unroll
    for (int k = 0; k < 4; k++) {
        float s = 0.f;
        #pragma unroll
        for (int f = 0; f < 7; f++) s += xr[f] * w[f * 128 + c0 + k];
        v[k] = s;
    }
    ((__half2*)(g_xph + (size_t)node * 128))[lane * 2]     = __floats2half2_rn(v[0], v[1]);
    ((__half2*)(g_xph + (size_t)node * 128))[lane * 2 + 1] = __floats2half2_rn(v[2], v[3]);
    int h  = c0 >> 6;
    const float* ai = att + h * 192;
    const float* aj = ai + 64;
    int cc = c0 & 63;
    float si_p = v[0] * ai[cc] + v[1] * ai[cc + 1] + v[2] * ai[cc + 2] + v[3] * ai[cc + 3];
    float sj_p = v[0] * aj[cc] + v[1] * aj[cc + 1] + v[2] * aj[cc + 2] + v[3] * aj[cc + 3];
    #pragma unroll
    for (int o = 8; o; o >>= 1) {
        si_p += __shfl_down_sync(0xffffffffu, si_p, o, 16);
        sj_p += __shfl_down_sync(0xffffffffu, sj_p, o, 16);
    }
    float si1 = __shfl_sync(0xffffffffu, si_p, 16);
    float sj1 = __shfl_sync(0xffffffffu, sj_p, 16);
    if (lane == 0) {
        g_si[node] = make_float2(si_p, si1);
        g_sj[node] = make_float2(sj_p, sj1);
    }
}

// ---- lin (layers 1,2): hh fp16 @ (W_hi + W_lo) -> g_xph + s-dots --------
__global__ void __launch_bounds__(256) lin128_wmma(const __half* __restrict__ hh,
                                                   int widx,
                                                   const float* __restrict__ att) {
    __shared__ __align__(32) unsigned char smem_raw[34816];
    __half* As  = (__half*)smem_raw;                 // [64][136]
    __half* Bhi = (__half*)(smem_raw + 17408);       // [32][136]
    __half* Blo = (__half*)(smem_raw + 26112);       // [32][136]
    float*  Cs  = (float*)smem_raw;                  // [64][132] after K loop

    const __half* whi = g_whi + widx * D * D;
    const __half* wlo = g_wlo + widx * D * D;

    int t = threadIdx.x;
    int wid = t >> 5, lane = t & 31;
    int row0 = blockIdx.x * 64;

    for (int i = t; i < 64 * 32; i += 256) {
        int r = i >> 5, g = i & 31;
        int row = row0 + r;
        uint2 v = make_uint2(0u, 0u);
        if (row < N_NODES) v = *(const uint2*)(hh + (size_t)row * 128 + g * 4);
        *(uint2*)(As + r * 136 + g * 4) = v;
    }

    wmma::fragment<wmma::accumulator, 16, 16, 16, float> c[4];
    #pragma unroll
    for (int j = 0; j < 4; j++) wmma::fill_fragment(c[j], 0.f);

    int m_tile = wid & 3;
    int n_half = wid >> 2;

    for (int kc = 0; kc < 4; kc++) {
        int k0 = kc * 32;
        for (int i = t; i < 32 * 32; i += 256) {
            int r = i >> 5, g = i & 31;
            *(uint2*)(Bhi + r * 136 + g * 4) = *(const uint2*)(whi + (size_t)(k0 + r) * 128 + g * 4);
            *(uint2*)(Blo + r * 136 + g * 4) = *(const uint2*)(wlo + (size_t)(k0 + r) * 128 + g * 4);
        }
        __syncthreads();
        #pragma unroll
        for (int kk = 0; kk < 2; kk++) {
            int k = k0 + kk * 16;
            wmma::fragment<wmma::matrix_a, 16, 16, 16, __half, wmma::row_major> a;
            wmma::load_matrix_sync(a, As + m_tile * 16 * 136 + k, 136);
            #pragma unroll
            for (int j = 0; j < 4; j++) {
                wmma::fragment<wmma::matrix_b, 16, 16, 16, __half, wmma::row_major> b;
                wmma::load_matrix_sync(b, Bhi + (kk * 16) * 136 + n_half * 64 + j * 16, 136);
                wmma::mma_sync(c[j], a, b, c[j]);
                wmma::load_matrix_sync(b, Blo + (kk * 16) * 136 + n_half * 64 + j * 16, 136);
                wmma::mma_sync(c[j], a, b, c[j]);
            }
        }
        __syncthreads();
    }

    #pragma unroll
    for (int j = 0; j < 4; j++)
        wmma::store_matrix_sync(Cs + m_tile * 16 * 132 + n_half * 64 + j * 16,
                                c[j], 132, wmma::mem_row_major);
    __syncthreads();

    for (int r8 = 0; r8 < 8; r8++) {
        int r = wid * 8 + r8;
        int row = row0 + r;
        if (row >= N_NODES) break;
        const float* cr = Cs + r * 132;
        float v0 = cr[lane * 4], v1 = cr[lane * 4 + 1];
        float v2 = cr[lane * 4 + 2], v3 = cr[lane * 4 + 3];
        ((__half2*)(g_xph + (size_t)row * 128))[lane * 2]     = __floats2half2_rn(v0, v1);
        ((__half2*)(g_xph + (size_t)row * 128))[lane * 2 + 1] = __floats2half2_rn(v2, v3);
        int c0 = lane * 4;
        int h  = c0 >> 6;
        const float* ai = att + h * 192;
        const float* aj = att + h * 192 + 64;
        int cc = c0 & 63;
        float si_p = v0 * ai[cc] + v1 * ai[cc + 1] + v2 * ai[cc + 2] + v3 * ai[cc + 3];
        float sj_p = v0 * aj[cc] + v1 * aj[cc + 1] + v2 * aj[cc + 2] + v3 * aj[cc + 3];
        #pragma unroll
        for (int o = 8; o; o >>= 1) {
            si_p += __shfl_down_sync(0xffffffffu, si_p, o, 16);
            sj_p += __shfl_down_sync(0xffffffffu, sj_p, o, 16);
        }
        float si1 = __shfl_sync(0xffffffffu, si_p, 16);
        float sj1 = __shfl_sync(0xffffffffu, sj_p, 16);
        if (lane == 0) {
            g_si[row] = make_float2(si_p, si1);
            g_sj[row] = make_float2(sj_p, sj1);
        }
    }
}

// ------- aggregate: warp/dst, 2-edge unrolled, sigmoid softmax -----------
// writes fp16 hh for ALL layers (pool reads fp16, accumulates fp32)
__device__ __forceinline__ float lrelu(float v) { return v > 0.f ? v : 0.2f * v; }

__global__ void __launch_bounds__(256) agg_kernel(const float* __restrict__ b, int layer) {
    int node = (blockIdx.x * blockDim.x + threadIdx.x) >> 5;
    int lane = threadIdx.x & 31;
    if (node >= N_NODES) return;
    int beg = g_off[node], end = g_off[node + 1];
    float2 si = g_si[node];
    const float2* seL = g_seS + (size_t)layer * N_EDGES;
    float4 acc = make_float4(0.f, 0.f, 0.f, 0.f);
    float sgn = (lane < 16) ? 1.f : -1.f;

    int i = beg;
    for (; i + 2 <= end; i += 2) {
        int s0 = g_srcs[i], s1 = g_srcs[i + 1];
        float2 se0 = seL[i], se1 = seL[i + 1];
        float2 sj0 = g_sj[s0], sj1 = g_sj[s1];
        uint2 r0 = ((const uint2*)(g_xph + (size_t)s0 * D))[lane];
        uint2 r1 = ((const uint2*)(g_xph + (size_t)s1 * D))[lane];

        float d0 = lrelu(si.x + sj0.x + se0.x) - lrelu(si.y + sj0.y + se0.y);
        float w0 = 1.f / (1.f + __expf(-sgn * d0));
        float2 f0 = __half22float2(*reinterpret_cast<__half2*>(&r0.x));
        float2 f1 = __half22float2(*reinterpret_cast<__half2*>(&r0.y));
        acc.x += w0 * f0.x; acc.y += w0 * f0.y;
        acc.z += w0 * f1.x; acc.w += w0 * f1.y;

        float d1 = lrelu(si.x + sj1.x + se1.x) - lrelu(si.y + sj1.y + se1.y);
        float w1 = 1.f / (1.f + __expf(-sgn * d1));
        float2 g0 = __half22float2(*reinterpret_cast<__half2*>(&r1.x));
        float2 g1 = __half22float2(*reinterpret_cast<__half2*>(&r1.y));
        acc.x += w1 * g0.x; acc.y += w1 * g0.y;
        acc.z += w1 * g1.x; acc.w += w1 * g1.y;
    }
    if (i < end) {
        int s0 = g_srcs[i];
        float2 se0 = seL[i];
        float2 sj0 = g_sj[s0];
        uint2 r0 = ((const uint2*)(g_xph + (size_t)s0 * D))[lane];
        float d0 = lrelu(si.x + sj0.x + se0.x) - lrelu(si.y + sj0.y + se0.y);
        float w0 = 1.f / (1.f + __expf(-sgn * d0));
        float2 f0 = __half22float2(*reinterpret_cast<__half2*>(&r0.x));
        float2 f1 = __half22float2(*reinterpret_cast<__half2*>(&r0.y));
        acc.x += w0 * f0.x; acc.y += w0 * f0.y;
        acc.z += w0 * f1.x; acc.w += w0 * f1.y;
    }
    float4 bv = ((const float4*)b)[lane];
    acc.x = fmaxf(acc.x + bv.x, 0.f);
    acc.y = fmaxf(acc.y + bv.y, 0.f);
    acc.z = fmaxf(acc.z + bv.z, 0.f);
    acc.w = fmaxf(acc.w + bv.w, 0.f);
    ((__half2*)(g_hh + (size_t)node * D))[lane * 2]     = __floats2half2_rn(acc.x, acc.y);
    ((__half2*)(g_hh + (size_t)node * D))[lane * 2 + 1] = __floats2half2_rn(acc.z, acc.w);
}

// --- mean pool: batch sorted, run-length accum; reads fp16 hh, fp32 acc --
__global__ void pool_kernel(const void* __restrict__ batch) {
    const int NPB = 128;
    int t  = threadIdx.x;
    int n0 = blockIdx.x * NPB;
    int is64 = g_flags[1];
    float acc = 0.f; int cur = -1; int run = 0;
    for (int k = 0; k < NPB; k++) {
        int n = n0 + k;
        if (n >= N_NODES) break;
        int g = is64 ? (int)((const long long*)batch)[n] : ((const int*)batch)[n];
        if (g != cur) {
            if (cur >= 0) {
                atomicAdd(&g_pool[cur * D + t], acc);
                if (t == 0) atomicAdd(&g_cnt[cur], (float)run);
            }
            acc = 0.f; run = 0; cur = g;
        }
        acc += __half2float(g_hh[(size_t)n * D + t]); run++;
    }
    if (cur >= 0) {
        atomicAdd(&g_pool[cur * D + t], acc);
        if (t == 0) atomicAdd(&g_cnt[cur], (float)run);
    }
}

// --------- final: warp per graph — mean, linear(128->2), log_softmax -----
__global__ void final_kernel(const float* __restrict__ wout,
                             const float* __restrict__ bout,
                             float* __restrict__ out) {
    int g    = (blockIdx.x * blockDim.x + threadIdx.x) >> 5;
    int lane = threadIdx.x & 31;
    if (g >= N_GRAPHS) return;
    float inv = 1.f / fmaxf(g_cnt[g], 1.f);
    float z0 = 0.f, z1 = 0.f;
    #pragma unroll
    for (int k = 0; k < 4; k++) {
        int c = lane + k * 32;
        float p = g_pool[g * D + c] * inv;
        z0 += p * wout[c * 2];
        z1 += p * wout[c * 2 + 1];
    }
    #pragma unroll
    for (int o = 16; o; o >>= 1) {
        z0 += __shfl_down_sync(0xffffffffu, z0, o);
        z1 += __shfl_down_sync(0xffffffffu, z1, o);
    }
    if (lane == 0) {
        z0 += bout[0]; z1 += bout[1];
        float m = fmaxf(z0, z1);
        float l = m + logf(expf(z0 - m) + expf(z1 - m));
        out[g * 2]     = z0 - l;
        out[g * 2 + 1] = z1 - l;
    }
}

// ------------------------------ launch -----------------------------------
extern "C" void kernel_launch(void* const* d_in, const int* in_sizes, int n_in,
                              void* d_out, int out_size) {
    const float* x     = (const float*)d_in[0];
    const void*  ei    = d_in[1];
    const float* ea    = (const float*)d_in[2];
    const void*  batch = d_in[3];
    const float* wl[3]  = { (const float*)d_in[4],  (const float*)d_in[8],  (const float*)d_in[12] };
    const float* we[3]  = { (const float*)d_in[5],  (const float*)d_in[9],  (const float*)d_in[13] };
    const float* att[3] = { (const float*)d_in[6],  (const float*)d_in[10], (const float*)d_in[14] };
    const float* bb[3]  = { (const float*)d_in[7],  (const float*)d_in[11], (const float*)d_in[15] };
    const float* wout = (const float*)d_in[16];
    const float* bout = (const float*)d_in[17];

    void* p_hh = nullptr;
    cudaGetSymbolAddress(&p_hh, g_hh);

    // init: zero scratch + dtype detect + attproj + wsplit (196 blocks)
    init_kernel<<<SCAN_B, 256>>>((const int*)ei, (const int*)batch,
                                 we[0], att[0], we[1], att[1], we[2], att[2],
                                 wl[1], wl[2]);

    // CSR build + sorted se (once per call)
    deg_kernel<<<(N_EDGES / 4 + 255) / 256, 256>>>(ei);
    scan1_kernel<<<SCAN_B, 256>>>();     // includes last-block scan of block sums
    scan3_kernel<<<SCAN_B, 256>>>();
    scatter_kernel<<<(N_EDGES / 2 + 255) / 256, 256>>>(ei, ea);

    for (int l = 0; l < 3; l++) {
        if (l == 0) {
            lin0s_kernel<<<(N_NODES * 32 + 255) / 256, 256>>>(x, wl[0], att[0]);
        } else {
            lin128_wmma<<<(N_NODES + 63) / 64, 256>>>((const __half*)p_hh, l - 1, att[l]);
        }
        agg_kernel<<<(N_NODES * 32 + 255) / 256, 256>>>(bb[l], l);
    }

    pool_kernel<<<(N_NODES + 127) / 128, 128>>>(batch);
    final_kernel<<<2, 1024>>>(wout, bout, (float*)d_out);
}